// round 9
// baseline (speedup 1.0000x reference)
#include <cuda_runtime.h>
#include <cuda_bf16.h>
#include <math.h>
#include <stdint.h>

#define BB 8
#define SS 2048
#define DIMV 240
#define NTOK (BB*SS)          // 16384
#define NEXP 8
#define NDEPTH 8
#define LATENTV 8
#define LOWD 80
#define LNEPS 1e-5f
#define PI_F 3.14159265358979323846f

// ------------------------- device scratch (padded for tail over-read) -------
__device__ __nv_bfloat16 g_hh[(size_t)NTOK * DIMV + 32];
__device__ __nv_bfloat16 g_hl[(size_t)NTOK * DIMV + 32];
__device__ float g_part[2][(size_t)NTOK * DIMV];
__device__ int   g_cnt[NDEPTH][NEXP];
__device__ int   g_list_tok[NEXP][NTOK];
__device__ float g_list_w[NEXP][NTOK];
__device__ int   g_list_k[NEXP][NTOK];
__device__ int   g_route_e[NTOK * 2];
__device__ float g_route_w[NTOK * 2];
__device__ float g_ce[240 * DIMV];
__device__ float g_se[240 * DIMV];
__device__ __nv_bfloat16 g_Bth[(size_t)NDEPTH * NEXP * DIMV * DIMV + 32];
__device__ __nv_bfloat16 g_Btl[(size_t)NDEPTH * NEXP * DIMV * DIMV + 32];

// ------------------------- PTX helpers --------------------------------------
__device__ __forceinline__ unsigned smem_u32(const void* p) {
    return (unsigned)__cvta_generic_to_shared(p);
}
__device__ __forceinline__ void cp16(unsigned dst, const void* src) {
    asm volatile("cp.async.ca.shared.global [%0], [%1], 16;\n" :: "r"(dst), "l"(src));
}
__device__ __forceinline__ void cp_commit() {
    asm volatile("cp.async.commit_group;\n" ::: "memory");
}
template<int N>
__device__ __forceinline__ void cp_wait() {
    asm volatile("cp.async.wait_group %0;\n" :: "n"(N) : "memory");
}
#define MMA_BF16(dd, A0, A1, A2, A3, B0, B1)                                   \
    asm volatile("mma.sync.aligned.m16n8k16.row.col.f32.bf16.bf16.f32 "        \
                 "{%0,%1,%2,%3},{%4,%5,%6,%7},{%8,%9},{%0,%1,%2,%3};"          \
                 : "+f"((dd)[0]), "+f"((dd)[1]), "+f"((dd)[2]), "+f"((dd)[3])  \
                 : "r"(A0), "r"(A1), "r"(A2), "r"(A3), "r"(B0), "r"(B1))

// ------------------------- routing finalize (one thread) --------------------
__device__ __forceinline__ void route_finalize(const float l[8], int L, int tok) {
    int e0 = 0; float b0 = l[0];
#pragma unroll
    for (int q = 1; q < 8; q++)
        if (l[q] > b0) { b0 = l[q]; e0 = q; }
    int e1 = -1; float b1 = -1e30f;
#pragma unroll
    for (int q = 0; q < 8; q++)
        if (q != e0 && l[q] > b1) { b1 = l[q]; e1 = q; }

    float w0 = 1.0f / (1.0f + expf(b1 - b0));
    float w1 = 1.0f - w0;

    int p0 = atomicAdd(&g_cnt[L][e0], 1);
    g_list_tok[e0][p0] = tok; g_list_w[e0][p0] = w0; g_list_k[e0][p0] = 0;
    int p1 = atomicAdd(&g_cnt[L][e1], 1);
    g_list_tok[e1][p1] = tok; g_list_w[e1][p1] = w1; g_list_k[e1][p1] = 1;

    g_route_e[tok * 2 + 0] = e0; g_route_e[tok * 2 + 1] = e1;
    g_route_w[tok * 2 + 0] = w0; g_route_w[tok * 2 + 1] = w1;
}

// ------------------------- setup: emb tables + counter zero -----------------
__global__ void setup_kernel(const float* __restrict__ roots,
                             const float* __restrict__ projW) {
    int s = blockIdx.x;
    int d = threadIdx.x;
    int j = d % LOWD;
    float emb = 0.f;
#pragma unroll
    for (int i = 0; i < LATENTV; i++)
        emb += roots[s * LATENTV + i] * projW[i * LOWD + j];
    g_ce[s * DIMV + d] = cosf(emb);
    g_se[s * DIMV + d] = sinf(emb);
    if (blockIdx.x == 0 && d < NDEPTH * NEXP)
        ((int*)g_cnt)[d] = 0;
}

// ------------------------- B convert + transpose ----------------------------
__global__ void bconv_kernel(const float* __restrict__ eW) {
    int le = blockIdx.y;
    int k0 = blockIdx.x * 16;
    const float* W = eW + (size_t)le * DIMV * DIMV;
    __nv_bfloat16* BH = g_Bth + (size_t)le * DIMV * DIMV;
    __nv_bfloat16* BL = g_Btl + (size_t)le * DIMV * DIMV;
    __shared__ float tile[16][241];
    for (int i = threadIdx.x; i < 16 * 240; i += 256) {
        int kk = i / 240, n = i - kk * 240;
        tile[kk][n] = W[(size_t)(k0 + kk) * DIMV + n];
    }
    __syncthreads();
    for (int i = threadIdx.x; i < 240 * 16; i += 256) {
        int n = i >> 4, kk = i & 15;
        float v = tile[kk][n];
        __nv_bfloat16 h = __float2bfloat16(v);
        float r = v - __bfloat162float(h);
        BH[(size_t)n * DIMV + k0 + kk] = h;
        BL[(size_t)n * DIMV + k0 + kk] = __float2bfloat16(r);
    }
}

// ------------------------- cycle block + fused gate(0) ----------------------
__global__ void cycle_kernel(const float* __restrict__ x,
                             const int* __restrict__ step,
                             const float* __restrict__ gW,
                             const float* __restrict__ gb) {
    __shared__ float s_x1[DIMV];
    __shared__ float s_se[DIMV];
    __shared__ float s_pump;
    __shared__ float s_acc[8];
    int t = blockIdx.x;
    int d = threadIdx.x;
    int lane = d & 31;
    int r = (t % SS) % 240;
    if (d == 0) s_pump = 0.8f * sinf((float)(*step) * 0.006f * 2.0f * PI_F);
    if (d < 8) s_acc[d] = 0.f;
    float ce = 0.f, se = 0.f;
    if (d < DIMV) {
        ce = g_ce[r * DIMV + d];
        se = g_se[r * DIMV + d];
        s_se[d] = se;
    }
    __syncthreads();
    if (d < DIMV)
        s_x1[d] = x[(size_t)t * DIMV + d] * (ce + s_pump);
    __syncthreads();

    float h = 0.f;
    if (d < DIMV) {
        int dm1 = (d + DIMV - 1) % DIMV;
        int dm2 = (d + DIMV - 2) % DIMV;
        h = (s_x1[d]
           + s_x1[dm1] * se
           + s_x1[dm2] * s_se[dm1] * ce) * (1.0f / 3.0f);
        __nv_bfloat16 hi = __float2bfloat16(h);
        g_hh[(size_t)t * DIMV + d] = hi;
        g_hl[(size_t)t * DIMV + d] = __float2bfloat16(h - __bfloat162float(hi));
    }

    float p[8];
    if (d < DIMV) {
        float4 w0 = *(const float4*)&gW[d * 8];
        float4 w1 = *(const float4*)&gW[d * 8 + 4];
        p[0] = h * w0.x; p[1] = h * w0.y; p[2] = h * w0.z; p[3] = h * w0.w;
        p[4] = h * w1.x; p[5] = h * w1.y; p[6] = h * w1.z; p[7] = h * w1.w;
    } else {
#pragma unroll
        for (int e = 0; e < 8; e++) p[e] = 0.f;
    }
#pragma unroll
    for (int e = 0; e < 8; e++)
#pragma unroll
        for (int o = 16; o > 0; o >>= 1)
            p[e] += __shfl_xor_sync(0xffffffffu, p[e], o);
    if (lane == 0) {
#pragma unroll
        for (int e = 0; e < 8; e++)
            atomicAdd(&s_acc[e], p[e]);
    }
    __syncthreads();
    if (d == 0) {
        float l[8];
#pragma unroll
        for (int e = 0; e < 8; e++) l[e] = s_acc[e] + gb[e];
        route_finalize(l, 0, t);
    }
}

// ------------------------- gate helper (warp; h in registers) ---------------
__device__ __forceinline__ void gate_from_regs(const float hh[8],
                                               const float* __restrict__ gW,
                                               const float* __restrict__ gb,
                                               int L, int tok, int lane) {
    float acc[8];
#pragma unroll
    for (int e = 0; e < 8; e++) acc[e] = 0.f;
#pragma unroll
    for (int jq = 0; jq < 8; jq++) {
        int d = lane + 32 * jq;
        if (d < DIMV) {
            float hv = hh[jq];
            float4 w0 = *(const float4*)&gW[d * 8];
            float4 w1 = *(const float4*)&gW[d * 8 + 4];
            acc[0] += hv * w0.x; acc[1] += hv * w0.y;
            acc[2] += hv * w0.z; acc[3] += hv * w0.w;
            acc[4] += hv * w1.x; acc[5] += hv * w1.y;
            acc[6] += hv * w1.z; acc[7] += hv * w1.w;
        }
    }
#pragma unroll
    for (int e = 0; e < 8; e++)
#pragma unroll
        for (int o = 16; o > 0; o >>= 1)
            acc[e] += __shfl_xor_sync(0xffffffffu, acc[e], o);

    if (lane == 0) {
        float l[8];
#pragma unroll
        for (int e = 0; e < 8; e++) l[e] = acc[e] + gb[e];
        route_finalize(l, L, tok);
    }
}

// ------------------------- tensor-core grouped GEMM (mma.sync bf16) ---------
// Tile 64 gathered tokens x 240 cols; K chunks of 32 (8 chunks, last half),
// double buffered; 2 blocks/SM. 8 warps: wm=wid&3 (16 rows), wn=wid>>2.
#define MT 64
#define NTILES (2 * NTOK / MT + NEXP)   // 520
#define AST 40                           // smem row stride in bf16 (80 B)
#define OFF_AH 0                         // [2][64][40] bf16 = 10240
#define OFF_AL 10240
#define OFF_BH 20480                     // [2][240][40] bf16 = 38400
#define OFF_BL 58880
#define SMEM_DYN 97280

__global__ __launch_bounds__(256, 2)
void moe_mma_kernel(int L) {
    int tileid = blockIdx.x;
    int e = 0, base = 0, cnt = 0, cum = 0;
#pragma unroll
    for (int q = 0; q < NEXP; q++) {
        int cq = g_cnt[L][q];
        int t = (cq + MT - 1) / MT;
        if (tileid >= cum && tileid < cum + t) { e = q; base = (tileid - cum) * MT; cnt = cq; }
        cum += t;
    }
    if (tileid >= cum) return;
    int mr = min(MT, cnt - base);

    extern __shared__ __align__(16) char dsm[];
    __shared__ int   s_tok[MT];
    __shared__ float s_w[MT];
    __shared__ int   s_k[MT];

    int tid = threadIdx.x, wid = tid >> 5, lane = tid & 31;

    if (tid < MT) {
        if (tid < mr) {
            s_tok[tid] = g_list_tok[e][base + tid];
            s_w[tid]   = g_list_w[e][base + tid];
            s_k[tid]   = g_list_k[e][base + tid];
        } else { s_tok[tid] = 0; s_w[tid] = 0.f; s_k[tid] = 0; }
    }
    __syncthreads();

    const __nv_bfloat16* BHsrc = g_Bth + (size_t)(L * NEXP + e) * DIMV * DIMV;
    const __nv_bfloat16* BLsrc = g_Btl + (size_t)(L * NEXP + e) * DIMV * DIMV;

    // chunk kc covers k = kc*32 .. +31 (kc==7: only first 16 valid/consumed;
    // loads over-read into the +32 global pad, never consumed by mma)
    auto issue = [&](int kc, int buf) {
        int abuf = buf * (MT * AST * 2);
        int bbuf = buf * (DIMV * AST * 2);
        int k0 = kc * 32;
        {   // A: 64 rows x 4 segs = 256 -> one cp16 pair per thread
            int row = tid >> 2, seg = tid & 3;
            size_t src = (size_t)s_tok[row] * DIMV + k0 + seg * 8;
            unsigned dst = (row * AST + seg * 8) * 2;
            cp16(smem_u32(dsm + OFF_AH + abuf + dst), g_hh + src);
            cp16(smem_u32(dsm + OFF_AL + abuf + dst), g_hl + src);
        }
#pragma unroll
        for (int j = 0; j < 4; j++) {    // B: 240 rows x 4 segs = 960
            int i = tid + j * 256;
            if (i < DIMV * 4) {
                int row = i >> 2, seg = i & 3;
                size_t src = (size_t)row * DIMV + k0 + seg * 8;
                unsigned dst = (row * AST + seg * 8) * 2;
                cp16(smem_u32(dsm + OFF_BH + bbuf + dst), BHsrc + src);
                cp16(smem_u32(dsm + OFF_BL + bbuf + dst), BLsrc + src);
            }
        }
        cp_commit();
    };

    int wm = wid & 3;
    int wn = wid >> 2;

    float acc[15][4];
#pragma unroll
    for (int nt = 0; nt < 15; nt++)
#pragma unroll
        for (int j = 0; j < 4; j++) acc[nt][j] = 0.f;

    issue(0, 0);

    int aoff0 = ((wm * 16 + (lane >> 2)) * AST + (lane & 3) * 2) * 2;
    int boff_lane = (lane >> 2) * AST * 2 + (lane & 3) * 4;

    for (int kc = 0; kc < 8; kc++) {
        int buf = kc & 1;
        if (kc + 1 < 8) { issue(kc + 1, buf ^ 1); cp_wait<1>(); }
        else            { cp_wait<0>(); }
        __syncthreads();

        const char* Ah = dsm + OFF_AH + buf * (MT * AST * 2);
        const char* Al = dsm + OFF_AL + buf * (MT * AST * 2);
        const char* Bh = dsm + OFF_BH + buf * (DIMV * AST * 2);
        const char* Bl = dsm + OFF_BL + buf * (DIMV * AST * 2);

        int nks = (kc < 7) ? 2 : 1;
#pragma unroll 2
        for (int ks = 0; ks < nks; ks++) {
            int ako = aoff0 + ks * 32;
            uint32_t ah0 = *(const uint32_t*)(Ah + ako);
            uint32_t ah1 = *(const uint32_t*)(Ah + ako + 8 * AST * 2);
            uint32_t ah2 = *(const uint32_t*)(Ah + ako + 16);
            uint32_t ah3 = *(const uint32_t*)(Ah + ako + 8 * AST * 2 + 16);
            uint32_t al0 = *(const uint32_t*)(Al + ako);
            uint32_t al1 = *(const uint32_t*)(Al + ako + 8 * AST * 2);
            uint32_t al2 = *(const uint32_t*)(Al + ako + 16);
            uint32_t al3 = *(const uint32_t*)(Al + ako + 8 * AST * 2 + 16);
#pragma unroll
            for (int nt = 0; nt < 15; nt++) {
                int bko = (wn * 120 + nt * 8) * AST * 2 + boff_lane + ks * 32;
                uint32_t bh0 = *(const uint32_t*)(Bh + bko);
                uint32_t bh1 = *(const uint32_t*)(Bh + bko + 16);
                uint32_t bl0 = *(const uint32_t*)(Bl + bko);
                uint32_t bl1 = *(const uint32_t*)(Bl + bko + 16);
                MMA_BF16(acc[nt], ah0, ah1, ah2, ah3, bh0, bh1);
                MMA_BF16(acc[nt], ah0, ah1, ah2, ah3, bl0, bl1);
                MMA_BF16(acc[nt], al0, al1, al2, al3, bh0, bh1);
            }
        }
        __syncthreads();
    }

    // ---- scaled stores straight from fragments ----
    int r0 = wm * 16 + (lane >> 2);
    int r1 = r0 + 8;
    int colb = wn * 120 + (lane & 3) * 2;
    bool ok0 = r0 < mr, ok1 = r1 < mr;
    float w0v = s_w[r0], w1v = s_w[r1];
    float* d0 = ok0 ? &g_part[s_k[r0]][(size_t)s_tok[r0] * DIMV] : 0;
    float* d1 = ok1 ? &g_part[s_k[r1]][(size_t)s_tok[r1] * DIMV] : 0;
#pragma unroll
    for (int nt = 0; nt < 15; nt++) {
        int col = colb + nt * 8;
        if (ok0) {
            float2 o; o.x = w0v * acc[nt][0]; o.y = w0v * acc[nt][1];
            *(float2*)&d0[col] = o;
        }
        if (ok1) {
            float2 o; o.x = w1v * acc[nt][2]; o.y = w1v * acc[nt][3];
            *(float2*)&d1[col] = o;
        }
    }
}

// ------------- fused: epilogue(L) [+ gate(L+1) if DO_GATE] -------------------
template<int DO_GATE>
__global__ void epi_gate_kernel(const float* __restrict__ eb,
                                const float* __restrict__ gamma,
                                const float* __restrict__ beta,
                                const float* __restrict__ gW,
                                const float* __restrict__ gb,
                                int Lnext) {
    int warp = threadIdx.x >> 5;
    int lane = threadIdx.x & 31;
    int tok  = blockIdx.x * 8 + warp;

    int   e0 = g_route_e[tok * 2 + 0], e1 = g_route_e[tok * 2 + 1];
    float w0 = g_route_w[tok * 2 + 0], w1 = g_route_w[tok * 2 + 1];

    const float* p0 = &g_part[0][(size_t)tok * DIMV];
    const float* p1 = &g_part[1][(size_t)tok * DIMV];

    float v[8];
    float sum = 0.f;
#pragma unroll
    for (int jq = 0; jq < 8; jq++) {
        int d = lane + 32 * jq;
        if (d < DIMV) {
            v[jq] = p0[d] + p1[d] + w0 * eb[e0 * DIMV + d] + w1 * eb[e1 * DIMV + d];
            sum += v[jq];
        } else v[jq] = 0.f;
    }
#pragma unroll
    for (int o = 16; o > 0; o >>= 1) sum += __shfl_xor_sync(0xffffffffu, sum, o);
    float mean = sum * (1.0f / DIMV);

    float vs = 0.f;
#pragma unroll
    for (int jq = 0; jq < 8; jq++) {
        int d = lane + 32 * jq;
        if (d < DIMV) { float c = v[jq] - mean; vs += c * c; }
    }
#pragma unroll
    for (int o = 16; o > 0; o >>= 1) vs += __shfl_xor_sync(0xffffffffu, vs, o);
    float inv = 1.0f / sqrtf(vs * (1.0f / DIMV) + LNEPS);

    float hh[8];
    __nv_bfloat16* hph = &g_hh[(size_t)tok * DIMV];
    __nv_bfloat16* hpl = &g_hl[(size_t)tok * DIMV];
#pragma unroll
    for (int jq = 0; jq < 8; jq++) {
        int d = lane + 32 * jq;
        if (d < DIMV) {
            float ln = (v[jq] - mean) * inv * gamma[d] + beta[d];
            float hv = v[jq] + ln;
            hh[jq] = hv;
            __nv_bfloat16 hi = __float2bfloat16(hv);
            hph[d] = hi;
            hpl[d] = __float2bfloat16(hv - __bfloat162float(hi));
        } else hh[jq] = 0.f;
    }

    if (DO_GATE)
        gate_from_regs(hh, gW, gb, Lnext, tok, lane);
}

// ------------------------- head (h = hi + lo) --------------------------------
__global__ void head_kernel(const float* __restrict__ hW,
                            const float* __restrict__ hb,
                            float* __restrict__ out) {
    int b = blockIdx.x;
    int tid = threadIdx.x;
    const __nv_bfloat16* hh = g_hh + (size_t)b * SS * DIMV;
    const __nv_bfloat16* hl = g_hl + (size_t)b * SS * DIMV;
    float acc = 0.f;
    for (int i = tid; i < SS * DIMV; i += 256) {
        float h = __bfloat162float(hh[i]) + __bfloat162float(hl[i]);
        acc += h * hW[i % DIMV];
    }
    __shared__ float red[256];
    red[tid] = acc;
    __syncthreads();
    for (int s2 = 128; s2 > 0; s2 >>= 1) {
        if (tid < s2) red[tid] += red[tid + s2];
        __syncthreads();
    }
    if (tid == 0) {
        float z = red[0] * (1.0f / SS) + hb[0];
        out[b] = 1.0f / (1.0f + expf(-z));
    }
}

// ------------------------- launch -------------------------------------------
extern "C" void kernel_launch(void* const* d_in, const int* in_sizes, int n_in,
                              void* d_out, int out_size) {
    const float* x     = (const float*)d_in[0];
    const int*   step  = (const int*)  d_in[1];
    const float* roots = (const float*)d_in[2];
    const float* projW = (const float*)d_in[3];
    const float* gW    = (const float*)d_in[4];
    const float* gb    = (const float*)d_in[5];
    const float* eW    = (const float*)d_in[6];
    const float* ebias = (const float*)d_in[7];
    const float* gamma = (const float*)d_in[8];
    const float* beta  = (const float*)d_in[9];
    const float* hW    = (const float*)d_in[10];
    const float* hb    = (const float*)d_in[11];
    float* out = (float*)d_out;

    cudaFuncSetAttribute(moe_mma_kernel,
                         cudaFuncAttributeMaxDynamicSharedMemorySize, SMEM_DYN);

    setup_kernel<<<240, DIMV>>>(roots, projW);
    {
        dim3 bg(15, NDEPTH * NEXP);
        bconv_kernel<<<bg, 256>>>(eW);
    }
    cycle_kernel<<<NTOK, 256>>>(x, step, gW, gb);

    for (int L = 0; L < NDEPTH; L++) {
        moe_mma_kernel<<<NTILES, 256, SMEM_DYN>>>(L);
        if (L + 1 < NDEPTH) {
            epi_gate_kernel<1><<<NTOK / 8, 256>>>(
                ebias + (size_t)L * NEXP * DIMV, gamma, beta,
                gW + (size_t)(L + 1) * DIMV * NEXP, gb + (size_t)(L + 1) * NEXP,
                L + 1);
        } else {
            epi_gate_kernel<0><<<NTOK / 8, 256>>>(
                ebias + (size_t)L * NEXP * DIMV, gamma, beta,
                gW, gb, 0);
        }
    }

    head_kernel<<<BB, 256>>>(hW, hb, out);
}

// round 10
// speedup vs baseline: 1.0014x; 1.0014x over previous
#include <cuda_runtime.h>
#include <cuda_bf16.h>
#include <math.h>
#include <stdint.h>

#define BB 8
#define SS 2048
#define DIMV 240
#define NTOK (BB*SS)          // 16384
#define NEXP 8
#define NDEPTH 8
#define LATENTV 8
#define LOWD 80
#define LNEPS 1e-5f
#define PI_F 3.14159265358979323846f

// ------------------------- device scratch ----------------------------------
__device__ __nv_bfloat16 g_hh[(size_t)NTOK * DIMV];   // h hi (bf16)
__device__ __nv_bfloat16 g_hl[(size_t)NTOK * DIMV];   // h lo (bf16 residual)
__device__ float g_part[2][(size_t)NTOK * DIMV];
__device__ int   g_cnt[NDEPTH][NEXP];
__device__ int   g_list_tok[NEXP][NTOK];
__device__ float g_list_w[NEXP][NTOK];
__device__ int   g_list_k[NEXP][NTOK];
__device__ int   g_route_e[NTOK * 2];
__device__ float g_route_w[NTOK * 2];
__device__ float g_ce[240 * DIMV];
__device__ float g_se[240 * DIMV];
__device__ __nv_bfloat16 g_Bth[(size_t)NDEPTH * NEXP * DIMV * DIMV];
__device__ __nv_bfloat16 g_Btl[(size_t)NDEPTH * NEXP * DIMV * DIMV];

// ------------------------- PTX helpers --------------------------------------
__device__ __forceinline__ unsigned smem_u32(const void* p) {
    return (unsigned)__cvta_generic_to_shared(p);
}
__device__ __forceinline__ void cp16(unsigned dst, const void* src) {
    asm volatile("cp.async.ca.shared.global [%0], [%1], 16;\n" :: "r"(dst), "l"(src));
}
__device__ __forceinline__ void cp_commit() {
    asm volatile("cp.async.commit_group;\n" ::: "memory");
}
template<int N>
__device__ __forceinline__ void cp_wait() {
    asm volatile("cp.async.wait_group %0;\n" :: "n"(N) : "memory");
}
#define MMA_BF16(dd, A0, A1, A2, A3, B0, B1)                                   \
    asm volatile("mma.sync.aligned.m16n8k16.row.col.f32.bf16.bf16.f32 "        \
                 "{%0,%1,%2,%3},{%4,%5,%6,%7},{%8,%9},{%0,%1,%2,%3};"          \
                 : "+f"((dd)[0]), "+f"((dd)[1]), "+f"((dd)[2]), "+f"((dd)[3])  \
                 : "r"(A0), "r"(A1), "r"(A2), "r"(A3), "r"(B0), "r"(B1))

// ------------------------- routing finalize (one thread) --------------------
__device__ __forceinline__ void route_finalize(const float l[8], int L, int tok) {
    int e0 = 0; float b0 = l[0];
#pragma unroll
    for (int q = 1; q < 8; q++)
        if (l[q] > b0) { b0 = l[q]; e0 = q; }
    int e1 = -1; float b1 = -1e30f;
#pragma unroll
    for (int q = 0; q < 8; q++)
        if (q != e0 && l[q] > b1) { b1 = l[q]; e1 = q; }

    float w0 = 1.0f / (1.0f + expf(b1 - b0));
    float w1 = 1.0f - w0;

    int p0 = atomicAdd(&g_cnt[L][e0], 1);
    g_list_tok[e0][p0] = tok; g_list_w[e0][p0] = w0; g_list_k[e0][p0] = 0;
    int p1 = atomicAdd(&g_cnt[L][e1], 1);
    g_list_tok[e1][p1] = tok; g_list_w[e1][p1] = w1; g_list_k[e1][p1] = 1;

    g_route_e[tok * 2 + 0] = e0; g_route_e[tok * 2 + 1] = e1;
    g_route_w[tok * 2 + 0] = w0; g_route_w[tok * 2 + 1] = w1;
}

// ------------------------- setup: emb tables + counter zero -----------------
__global__ void setup_kernel(const float* __restrict__ roots,
                             const float* __restrict__ projW) {
    int s = blockIdx.x;
    int d = threadIdx.x;
    int j = d % LOWD;
    float emb = 0.f;
#pragma unroll
    for (int i = 0; i < LATENTV; i++)
        emb += roots[s * LATENTV + i] * projW[i * LOWD + j];
    g_ce[s * DIMV + d] = cosf(emb);
    g_se[s * DIMV + d] = sinf(emb);
    if (blockIdx.x == 0 && d < NDEPTH * NEXP)
        ((int*)g_cnt)[d] = 0;
}

// ------------------------- B convert + transpose ----------------------------
// grid (15, 64): blockIdx.x = k-slice, blockIdx.y = L*8+e
__global__ void bconv_kernel(const float* __restrict__ eW) {
    int le = blockIdx.y;
    int k0 = blockIdx.x * 16;
    const float* W = eW + (size_t)le * DIMV * DIMV;
    __nv_bfloat16* BH = g_Bth + (size_t)le * DIMV * DIMV;
    __nv_bfloat16* BL = g_Btl + (size_t)le * DIMV * DIMV;
    __shared__ float tile[16][241];
    for (int i = threadIdx.x; i < 16 * 240; i += 256) {
        int kk = i / 240, n = i - kk * 240;
        tile[kk][n] = W[(size_t)(k0 + kk) * DIMV + n];
    }
    __syncthreads();
    for (int i = threadIdx.x; i < 240 * 16; i += 256) {
        int n = i >> 4, kk = i & 15;
        float v = tile[kk][n];
        __nv_bfloat16 h = __float2bfloat16(v);
        float r = v - __bfloat162float(h);
        BH[(size_t)n * DIMV + k0 + kk] = h;
        BL[(size_t)n * DIMV + k0 + kk] = __float2bfloat16(r);
    }
}

// ------------------------- cycle block + fused gate(0) ----------------------
__global__ void cycle_kernel(const float* __restrict__ x,
                             const int* __restrict__ step,
                             const float* __restrict__ gW,
                             const float* __restrict__ gb) {
    __shared__ float s_x1[DIMV];
    __shared__ float s_se[DIMV];
    __shared__ float s_pump;
    __shared__ float s_acc[8];
    int t = blockIdx.x;
    int d = threadIdx.x;
    int lane = d & 31;
    int r = (t % SS) % 240;
    if (d == 0) s_pump = 0.8f * sinf((float)(*step) * 0.006f * 2.0f * PI_F);
    if (d < 8) s_acc[d] = 0.f;
    float ce = 0.f, se = 0.f;
    if (d < DIMV) {
        ce = g_ce[r * DIMV + d];
        se = g_se[r * DIMV + d];
        s_se[d] = se;
    }
    __syncthreads();
    if (d < DIMV)
        s_x1[d] = x[(size_t)t * DIMV + d] * (ce + s_pump);
    __syncthreads();

    float h = 0.f;
    if (d < DIMV) {
        int dm1 = (d + DIMV - 1) % DIMV;
        int dm2 = (d + DIMV - 2) % DIMV;
        h = (s_x1[d]
           + s_x1[dm1] * se
           + s_x1[dm2] * s_se[dm1] * ce) * (1.0f / 3.0f);
        __nv_bfloat16 hi = __float2bfloat16(h);
        g_hh[(size_t)t * DIMV + d] = hi;
        g_hl[(size_t)t * DIMV + d] = __float2bfloat16(h - __bfloat162float(hi));
    }

    float p[8];
    if (d < DIMV) {
        float4 w0 = *(const float4*)&gW[d * 8];
        float4 w1 = *(const float4*)&gW[d * 8 + 4];
        p[0] = h * w0.x; p[1] = h * w0.y; p[2] = h * w0.z; p[3] = h * w0.w;
        p[4] = h * w1.x; p[5] = h * w1.y; p[6] = h * w1.z; p[7] = h * w1.w;
    } else {
#pragma unroll
        for (int e = 0; e < 8; e++) p[e] = 0.f;
    }
#pragma unroll
    for (int e = 0; e < 8; e++)
#pragma unroll
        for (int o = 16; o > 0; o >>= 1)
            p[e] += __shfl_xor_sync(0xffffffffu, p[e], o);
    if (lane == 0) {
#pragma unroll
        for (int e = 0; e < 8; e++)
            atomicAdd(&s_acc[e], p[e]);
    }
    __syncthreads();
    if (d == 0) {
        float l[8];
#pragma unroll
        for (int e = 0; e < 8; e++) l[e] = s_acc[e] + gb[e];
        route_finalize(l, 0, t);
    }
}

// ------------------------- gate helper (warp; h in registers) ---------------
__device__ __forceinline__ void gate_from_regs(const float hh[8],
                                               const float* __restrict__ gW,
                                               const float* __restrict__ gb,
                                               int L, int tok, int lane) {
    float acc[8];
#pragma unroll
    for (int e = 0; e < 8; e++) acc[e] = 0.f;
#pragma unroll
    for (int jq = 0; jq < 8; jq++) {
        int d = lane + 32 * jq;
        if (d < DIMV) {
            float hv = hh[jq];
            float4 w0 = *(const float4*)&gW[d * 8];
            float4 w1 = *(const float4*)&gW[d * 8 + 4];
            acc[0] += hv * w0.x; acc[1] += hv * w0.y;
            acc[2] += hv * w0.z; acc[3] += hv * w0.w;
            acc[4] += hv * w1.x; acc[5] += hv * w1.y;
            acc[6] += hv * w1.z; acc[7] += hv * w1.w;
        }
    }
#pragma unroll
    for (int e = 0; e < 8; e++)
#pragma unroll
        for (int o = 16; o > 0; o >>= 1)
            acc[e] += __shfl_xor_sync(0xffffffffu, acc[e], o);

    if (lane == 0) {
        float l[8];
#pragma unroll
        for (int e = 0; e < 8; e++) l[e] = acc[e] + gb[e];
        route_finalize(l, L, tok);
    }
}

// ------------------------- tensor-core grouped GEMM (mma.sync bf16) ---------
// R7's proven config: tile 64 tokens x 240 cols; K chunks of 48, double
// buffered; 8 warps: wm = wid&3 (16-row m-tile), wn = wid>>2 (120-col half).
#define MT 64
#define NTILES (2 * NTOK / MT + NEXP)   // 520
#define KC 48
#define AST 56                           // smem row stride in bf16 (112 B)
#define OFF_AH 0                         // [2][64][56] bf16 = 14336
#define OFF_AL 14336
#define OFF_BH 28672                     // [2][240][56] bf16 = 53760
#define OFF_BL 82432
#define SMEM_DYN 136192

__global__ __launch_bounds__(256, 1)
void moe_mma_kernel(int L) {
    int tileid = blockIdx.x;
    int e = 0, base = 0, cnt = 0, cum = 0;
#pragma unroll
    for (int q = 0; q < NEXP; q++) {
        int cq = g_cnt[L][q];
        int t = (cq + MT - 1) / MT;
        if (tileid >= cum && tileid < cum + t) { e = q; base = (tileid - cum) * MT; cnt = cq; }
        cum += t;
    }
    if (tileid >= cum) return;
    int mr = min(MT, cnt - base);

    extern __shared__ __align__(16) char dsm[];
    __shared__ int   s_tok[MT];
    __shared__ float s_w[MT];
    __shared__ int   s_k[MT];

    int tid = threadIdx.x, wid = tid >> 5, lane = tid & 31;

    if (tid < MT) {
        if (tid < mr) {
            s_tok[tid] = g_list_tok[e][base + tid];
            s_w[tid]   = g_list_w[e][base + tid];
            s_k[tid]   = g_list_k[e][base + tid];
        } else { s_tok[tid] = 0; s_w[tid] = 0.f; s_k[tid] = 0; }
    }
    __syncthreads();

    const __nv_bfloat16* BHsrc = g_Bth + (size_t)(L * NEXP + e) * DIMV * DIMV;
    const __nv_bfloat16* BLsrc = g_Btl + (size_t)(L * NEXP + e) * DIMV * DIMV;

    auto issue = [&](int kc, int buf) {
        int abuf = buf * (MT * AST * 2);
        int bbuf = buf * (DIMV * AST * 2);
        for (int i = tid; i < MT * 6; i += 256) {
            int row = i / 6, seg = i - row * 6;
            size_t src = (size_t)s_tok[row] * DIMV + kc * KC + seg * 8;
            unsigned dst = (row * AST + seg * 8) * 2;
            cp16(smem_u32(dsm + OFF_AH + abuf + dst), g_hh + src);
            cp16(smem_u32(dsm + OFF_AL + abuf + dst), g_hl + src);
        }
        for (int i = tid; i < DIMV * 6; i += 256) {
            int row = i / 6, seg = i - row * 6;
            size_t src = (size_t)row * DIMV + kc * KC + seg * 8;
            unsigned dst = (row * AST + seg * 8) * 2;
            cp16(smem_u32(dsm + OFF_BH + bbuf + dst), BHsrc + src);
            cp16(smem_u32(dsm + OFF_BL + bbuf + dst), BLsrc + src);
        }
        cp_commit();
    };

    int wm = wid & 3;
    int wn = wid >> 2;

    float acc[15][4];
#pragma unroll
    for (int nt = 0; nt < 15; nt++)
#pragma unroll
        for (int j = 0; j < 4; j++) acc[nt][j] = 0.f;

    issue(0, 0);

    int aoff_base = ((wm * 16 + (lane >> 2)) * AST + (lane & 3) * 2) * 2;
    int boff_lane = (lane >> 2) * AST * 2 + (lane & 3) * 4;

    for (int kc = 0; kc < 5; kc++) {
        int buf = kc & 1;
        if (kc + 1 < 5) { issue(kc + 1, buf ^ 1); cp_wait<1>(); }
        else            { cp_wait<0>(); }
        __syncthreads();

        const char* Ah = dsm + OFF_AH + buf * (MT * AST * 2);
        const char* Al = dsm + OFF_AL + buf * (MT * AST * 2);
        const char* Bh = dsm + OFF_BH + buf * (DIMV * AST * 2);
        const char* Bl = dsm + OFF_BL + buf * (DIMV * AST * 2);

#pragma unroll
        for (int ks = 0; ks < 3; ks++) {
            int ako = aoff_base + ks * 32;
            uint32_t ah0 = *(const uint32_t*)(Ah + ako);
            uint32_t ah1 = *(const uint32_t*)(Ah + ako + 8 * AST * 2);
            uint32_t ah2 = *(const uint32_t*)(Ah + ako + 16);
            uint32_t ah3 = *(const uint32_t*)(Ah + ako + 8 * AST * 2 + 16);
            uint32_t al0 = *(const uint32_t*)(Al + ako);
            uint32_t al1 = *(const uint32_t*)(Al + ako + 8 * AST * 2);
            uint32_t al2 = *(const uint32_t*)(Al + ako + 16);
            uint32_t al3 = *(const uint32_t*)(Al + ako + 8 * AST * 2 + 16);
#pragma unroll
            for (int nt = 0; nt < 15; nt++) {
                int bko = (wn * 120 + nt * 8) * AST * 2 + boff_lane + ks * 32;
                uint32_t bh0 = *(const uint32_t*)(Bh + bko);
                uint32_t bh1 = *(const uint32_t*)(Bh + bko + 16);
                uint32_t bl0 = *(const uint32_t*)(Bl + bko);
                uint32_t bl1 = *(const uint32_t*)(Bl + bko + 16);
                MMA_BF16(acc[nt], ah0, ah1, ah2, ah3, bh0, bh1);
                MMA_BF16(acc[nt], ah0, ah1, ah2, ah3, bl0, bl1);
                MMA_BF16(acc[nt], al0, al1, al2, al3, bh0, bh1);
            }
        }
        __syncthreads();
    }

    // ---- scaled stores straight from fragments ----
    int r0 = wm * 16 + (lane >> 2);
    int r1 = r0 + 8;
    int colb = wn * 120 + (lane & 3) * 2;
    bool ok0 = r0 < mr, ok1 = r1 < mr;
    float w0v = s_w[r0], w1v = s_w[r1];
    float* d0 = ok0 ? &g_part[s_k[r0]][(size_t)s_tok[r0] * DIMV] : 0;
    float* d1 = ok1 ? &g_part[s_k[r1]][(size_t)s_tok[r1] * DIMV] : 0;
#pragma unroll
    for (int nt = 0; nt < 15; nt++) {
        int col = colb + nt * 8;
        if (ok0) {
            float2 o; o.x = w0v * acc[nt][0]; o.y = w0v * acc[nt][1];
            *(float2*)&d0[col] = o;
        }
        if (ok1) {
            float2 o; o.x = w1v * acc[nt][2]; o.y = w1v * acc[nt][3];
            *(float2*)&d1[col] = o;
        }
    }
}

// ------------- fused: epilogue(L) [+ gate(L+1) if DO_GATE] -------------------
template<int DO_GATE>
__global__ void epi_gate_kernel(const float* __restrict__ eb,
                                const float* __restrict__ gamma,
                                const float* __restrict__ beta,
                                const float* __restrict__ gW,
                                const float* __restrict__ gb,
                                int Lnext) {
    int warp = threadIdx.x >> 5;
    int lane = threadIdx.x & 31;
    int tok  = blockIdx.x * 8 + warp;

    int   e0 = g_route_e[tok * 2 + 0], e1 = g_route_e[tok * 2 + 1];
    float w0 = g_route_w[tok * 2 + 0], w1 = g_route_w[tok * 2 + 1];

    const float* p0 = &g_part[0][(size_t)tok * DIMV];
    const float* p1 = &g_part[1][(size_t)tok * DIMV];

    float v[8];
    float sum = 0.f;
#pragma unroll
    for (int jq = 0; jq < 8; jq++) {
        int d = lane + 32 * jq;
        if (d < DIMV) {
            v[jq] = p0[d] + p1[d] + w0 * eb[e0 * DIMV + d] + w1 * eb[e1 * DIMV + d];
            sum += v[jq];
        } else v[jq] = 0.f;
    }
#pragma unroll
    for (int o = 16; o > 0; o >>= 1) sum += __shfl_xor_sync(0xffffffffu, sum, o);
    float mean = sum * (1.0f / DIMV);

    float vs = 0.f;
#pragma unroll
    for (int jq = 0; jq < 8; jq++) {
        int d = lane + 32 * jq;
        if (d < DIMV) { float c = v[jq] - mean; vs += c * c; }
    }
#pragma unroll
    for (int o = 16; o > 0; o >>= 1) vs += __shfl_xor_sync(0xffffffffu, vs, o);
    float inv = 1.0f / sqrtf(vs * (1.0f / DIMV) + LNEPS);

    float hh[8];
    __nv_bfloat16* hph = &g_hh[(size_t)tok * DIMV];
    __nv_bfloat16* hpl = &g_hl[(size_t)tok * DIMV];
#pragma unroll
    for (int jq = 0; jq < 8; jq++) {
        int d = lane + 32 * jq;
        if (d < DIMV) {
            float ln = (v[jq] - mean) * inv * gamma[d] + beta[d];
            float hv = v[jq] + ln;
            hh[jq] = hv;
            __nv_bfloat16 hi = __float2bfloat16(hv);
            hph[d] = hi;
            hpl[d] = __float2bfloat16(hv - __bfloat162float(hi));
        } else hh[jq] = 0.f;
    }

    if (DO_GATE)
        gate_from_regs(hh, gW, gb, Lnext, tok, lane);
}

// ------------------------- head (h = hi + lo) --------------------------------
__global__ void head_kernel(const float* __restrict__ hW,
                            const float* __restrict__ hb,
                            float* __restrict__ out) {
    int b = blockIdx.x;
    int tid = threadIdx.x;
    const __nv_bfloat16* hh = g_hh + (size_t)b * SS * DIMV;
    const __nv_bfloat16* hl = g_hl + (size_t)b * SS * DIMV;
    float acc = 0.f;
    for (int i = tid; i < SS * DIMV; i += 256) {
        float h = __bfloat162float(hh[i]) + __bfloat162float(hl[i]);
        acc += h * hW[i % DIMV];
    }
    __shared__ float red[256];
    red[tid] = acc;
    __syncthreads();
    for (int s2 = 128; s2 > 0; s2 >>= 1) {
        if (tid < s2) red[tid] += red[tid + s2];
        __syncthreads();
    }
    if (tid == 0) {
        float z = red[0] * (1.0f / SS) + hb[0];
        out[b] = 1.0f / (1.0f + expf(-z));
    }
}

// ------------------------- launch -------------------------------------------
extern "C" void kernel_launch(void* const* d_in, const int* in_sizes, int n_in,
                              void* d_out, int out_size) {
    const float* x     = (const float*)d_in[0];
    const int*   step  = (const int*)  d_in[1];
    const float* roots = (const float*)d_in[2];
    const float* projW = (const float*)d_in[3];
    const float* gW    = (const float*)d_in[4];
    const float* gb    = (const float*)d_in[5];
    const float* eW    = (const float*)d_in[6];
    const float* ebias = (const float*)d_in[7];
    const float* gamma = (const float*)d_in[8];
    const float* beta  = (const float*)d_in[9];
    const float* hW    = (const float*)d_in[10];
    const float* hb    = (const float*)d_in[11];
    float* out = (float*)d_out;

    cudaFuncSetAttribute(moe_mma_kernel,
                         cudaFuncAttributeMaxDynamicSharedMemorySize, SMEM_DYN);

    setup_kernel<<<240, DIMV>>>(roots, projW);
    {
        dim3 bg(15, NDEPTH * NEXP);
        bconv_kernel<<<bg, 256>>>(eW);
    }
    cycle_kernel<<<NTOK, 256>>>(x, step, gW, gb);

    for (int L = 0; L < NDEPTH; L++) {
        moe_mma_kernel<<<NTILES, 256, SMEM_DYN>>>(L);
        if (L + 1 < NDEPTH) {
            epi_gate_kernel<1><<<NTOK / 8, 256>>>(
                ebias + (size_t)L * NEXP * DIMV, gamma, beta,
                gW + (size_t)(L + 1) * DIMV * NEXP, gb + (size_t)(L + 1) * NEXP,
                L + 1);
        } else {
            epi_gate_kernel<0><<<NTOK / 8, 256>>>(
                ebias + (size_t)L * NEXP * DIMV, gamma, beta,
                gW, gb, 0);
        }
    }

    head_kernel<<<BB, 256>>>(hW, hb, out);
}

// round 11
// speedup vs baseline: 1.1240x; 1.1224x over previous
#include <cuda_runtime.h>
#include <cuda_bf16.h>
#include <math.h>
#include <stdint.h>

#define BB 8
#define SS 2048
#define DIMV 240
#define NTOK (BB*SS)          // 16384
#define NEXP 8
#define NDEPTH 8
#define LATENTV 8
#define LOWD 80
#define LNEPS 1e-5f
#define PI_F 3.14159265358979323846f

// ------------------------- device scratch ----------------------------------
__device__ __nv_bfloat16 g_hh[(size_t)NTOK * DIMV];   // h hi (bf16)
__device__ __nv_bfloat16 g_hl[(size_t)NTOK * DIMV];   // h lo (bf16 residual)
__device__ float g_part[2][(size_t)NTOK * DIMV];
__device__ int   g_cnt[NDEPTH][NEXP];
__device__ int   g_list_tok[NEXP][NTOK];
__device__ float g_list_w[NEXP][NTOK];
__device__ int   g_list_k[NEXP][NTOK];
__device__ int   g_route_e[NTOK * 2];
__device__ float g_route_w[NTOK * 2];
__device__ float g_ce[240 * DIMV];
__device__ float g_se[240 * DIMV];
__device__ __nv_bfloat16 g_Bth[(size_t)NDEPTH * NEXP * DIMV * DIMV];
__device__ __nv_bfloat16 g_Btl[(size_t)NDEPTH * NEXP * DIMV * DIMV];

// ------------------------- PTX helpers --------------------------------------
__device__ __forceinline__ unsigned smem_u32(const void* p) {
    return (unsigned)__cvta_generic_to_shared(p);
}
__device__ __forceinline__ void cp16(unsigned dst, const void* src) {
    asm volatile("cp.async.ca.shared.global [%0], [%1], 16;\n" :: "r"(dst), "l"(src));
}
__device__ __forceinline__ void cp_commit() {
    asm volatile("cp.async.commit_group;\n" ::: "memory");
}
template<int N>
__device__ __forceinline__ void cp_wait() {
    asm volatile("cp.async.wait_group %0;\n" :: "n"(N) : "memory");
}
__device__ __forceinline__ void ldsm4(uint32_t* r, uint32_t addr) {
    asm volatile("ldmatrix.sync.aligned.m8n8.x4.shared.b16 {%0,%1,%2,%3}, [%4];"
                 : "=r"(r[0]), "=r"(r[1]), "=r"(r[2]), "=r"(r[3]) : "r"(addr));
}
__device__ __forceinline__ void ldsm2(uint32_t* r, uint32_t addr) {
    asm volatile("ldmatrix.sync.aligned.m8n8.x2.shared.b16 {%0,%1}, [%2];"
                 : "=r"(r[0]), "=r"(r[1]) : "r"(addr));
}
#define MMA_BF16(dd, A0, A1, A2, A3, B0, B1)                                   \
    asm volatile("mma.sync.aligned.m16n8k16.row.col.f32.bf16.bf16.f32 "        \
                 "{%0,%1,%2,%3},{%4,%5,%6,%7},{%8,%9},{%0,%1,%2,%3};"          \
                 : "+f"((dd)[0]), "+f"((dd)[1]), "+f"((dd)[2]), "+f"((dd)[3])  \
                 : "r"(A0), "r"(A1), "r"(A2), "r"(A3), "r"(B0), "r"(B1))

// ------------------------- routing finalize (one thread) --------------------
__device__ __forceinline__ void route_finalize(const float l[8], int L, int tok) {
    int e0 = 0; float b0 = l[0];
#pragma unroll
    for (int q = 1; q < 8; q++)
        if (l[q] > b0) { b0 = l[q]; e0 = q; }
    int e1 = -1; float b1 = -1e30f;
#pragma unroll
    for (int q = 0; q < 8; q++)
        if (q != e0 && l[q] > b1) { b1 = l[q]; e1 = q; }

    float w0 = 1.0f / (1.0f + expf(b1 - b0));
    float w1 = 1.0f - w0;

    int p0 = atomicAdd(&g_cnt[L][e0], 1);
    g_list_tok[e0][p0] = tok; g_list_w[e0][p0] = w0; g_list_k[e0][p0] = 0;
    int p1 = atomicAdd(&g_cnt[L][e1], 1);
    g_list_tok[e1][p1] = tok; g_list_w[e1][p1] = w1; g_list_k[e1][p1] = 1;

    g_route_e[tok * 2 + 0] = e0; g_route_e[tok * 2 + 1] = e1;
    g_route_w[tok * 2 + 0] = w0; g_route_w[tok * 2 + 1] = w1;
}

// ------------------------- setup: emb tables + counter zero -----------------
__global__ void setup_kernel(const float* __restrict__ roots,
                             const float* __restrict__ projW) {
    int s = blockIdx.x;
    int d = threadIdx.x;
    int j = d % LOWD;
    float emb = 0.f;
#pragma unroll
    for (int i = 0; i < LATENTV; i++)
        emb += roots[s * LATENTV + i] * projW[i * LOWD + j];
    g_ce[s * DIMV + d] = cosf(emb);
    g_se[s * DIMV + d] = sinf(emb);
    if (blockIdx.x == 0 && d < NDEPTH * NEXP)
        ((int*)g_cnt)[d] = 0;
}

// ------------------------- B convert + transpose ----------------------------
__global__ void bconv_kernel(const float* __restrict__ eW) {
    int le = blockIdx.y;
    int k0 = blockIdx.x * 16;
    const float* W = eW + (size_t)le * DIMV * DIMV;
    __nv_bfloat16* BH = g_Bth + (size_t)le * DIMV * DIMV;
    __nv_bfloat16* BL = g_Btl + (size_t)le * DIMV * DIMV;
    __shared__ float tile[16][241];
    for (int i = threadIdx.x; i < 16 * 240; i += 256) {
        int kk = i / 240, n = i - kk * 240;
        tile[kk][n] = W[(size_t)(k0 + kk) * DIMV + n];
    }
    __syncthreads();
    for (int i = threadIdx.x; i < 240 * 16; i += 256) {
        int n = i >> 4, kk = i & 15;
        float v = tile[kk][n];
        __nv_bfloat16 h = __float2bfloat16(v);
        float r = v - __bfloat162float(h);
        BH[(size_t)n * DIMV + k0 + kk] = h;
        BL[(size_t)n * DIMV + k0 + kk] = __float2bfloat16(r);
    }
}

// ------------------------- cycle block + fused gate(0) ----------------------
__global__ void cycle_kernel(const float* __restrict__ x,
                             const int* __restrict__ step,
                             const float* __restrict__ gW,
                             const float* __restrict__ gb) {
    __shared__ float s_x1[DIMV];
    __shared__ float s_se[DIMV];
    __shared__ float s_pump;
    __shared__ float s_acc[8];
    int t = blockIdx.x;
    int d = threadIdx.x;
    int lane = d & 31;
    int r = (t % SS) % 240;
    if (d == 0) s_pump = 0.8f * sinf((float)(*step) * 0.006f * 2.0f * PI_F);
    if (d < 8) s_acc[d] = 0.f;
    float ce = 0.f, se = 0.f;
    if (d < DIMV) {
        ce = g_ce[r * DIMV + d];
        se = g_se[r * DIMV + d];
        s_se[d] = se;
    }
    __syncthreads();
    if (d < DIMV)
        s_x1[d] = x[(size_t)t * DIMV + d] * (ce + s_pump);
    __syncthreads();

    float h = 0.f;
    if (d < DIMV) {
        int dm1 = (d + DIMV - 1) % DIMV;
        int dm2 = (d + DIMV - 2) % DIMV;
        h = (s_x1[d]
           + s_x1[dm1] * se
           + s_x1[dm2] * s_se[dm1] * ce) * (1.0f / 3.0f);
        __nv_bfloat16 hi = __float2bfloat16(h);
        g_hh[(size_t)t * DIMV + d] = hi;
        g_hl[(size_t)t * DIMV + d] = __float2bfloat16(h - __bfloat162float(hi));
    }

    float p[8];
    if (d < DIMV) {
        float4 w0 = *(const float4*)&gW[d * 8];
        float4 w1 = *(const float4*)&gW[d * 8 + 4];
        p[0] = h * w0.x; p[1] = h * w0.y; p[2] = h * w0.z; p[3] = h * w0.w;
        p[4] = h * w1.x; p[5] = h * w1.y; p[6] = h * w1.z; p[7] = h * w1.w;
    } else {
#pragma unroll
        for (int e = 0; e < 8; e++) p[e] = 0.f;
    }
#pragma unroll
    for (int e = 0; e < 8; e++)
#pragma unroll
        for (int o = 16; o > 0; o >>= 1)
            p[e] += __shfl_xor_sync(0xffffffffu, p[e], o);
    if (lane == 0) {
#pragma unroll
        for (int e = 0; e < 8; e++)
            atomicAdd(&s_acc[e], p[e]);
    }
    __syncthreads();
    if (d == 0) {
        float l[8];
#pragma unroll
        for (int e = 0; e < 8; e++) l[e] = s_acc[e] + gb[e];
        route_finalize(l, 0, t);
    }
}

// ------------------------- gate helper (warp; h in registers) ---------------
__device__ __forceinline__ void gate_from_regs(const float hh[8],
                                               const float* __restrict__ gW,
                                               const float* __restrict__ gb,
                                               int L, int tok, int lane) {
    float acc[8];
#pragma unroll
    for (int e = 0; e < 8; e++) acc[e] = 0.f;
#pragma unroll
    for (int jq = 0; jq < 8; jq++) {
        int d = lane + 32 * jq;
        if (d < DIMV) {
            float hv = hh[jq];
            float4 w0 = *(const float4*)&gW[d * 8];
            float4 w1 = *(const float4*)&gW[d * 8 + 4];
            acc[0] += hv * w0.x; acc[1] += hv * w0.y;
            acc[2] += hv * w0.z; acc[3] += hv * w0.w;
            acc[4] += hv * w1.x; acc[5] += hv * w1.y;
            acc[6] += hv * w1.z; acc[7] += hv * w1.w;
        }
    }
#pragma unroll
    for (int e = 0; e < 8; e++)
#pragma unroll
        for (int o = 16; o > 0; o >>= 1)
            acc[e] += __shfl_xor_sync(0xffffffffu, acc[e], o);

    if (lane == 0) {
        float l[8];
#pragma unroll
        for (int e = 0; e < 8; e++) l[e] = acc[e] + gb[e];
        route_finalize(l, L, tok);
    }
}

// ------------------------- tensor-core grouped GEMM (mma.sync bf16) ---------
// R8 config (best measured): tile 128 tokens x 240 cols; KC=48, double
// buffered. ldmatrix fragment loads (this round's single change).
#define MT 128
#define NTILES (2 * NTOK / MT + NEXP)   // 264
#define KC 48
#define AST 56                           // smem row stride in bf16 (112 B)
#define ASTB (AST * 2)                   // 112 bytes
#define OFF_AH 0                         // [2][128][56] bf16 = 28672
#define OFF_AL 28672
#define OFF_BH 57344                     // [2][240][56] bf16 = 53760
#define OFF_BL 111104
#define SMEM_DYN 164864
#define ASTAGE (MT * ASTB)               // 14336
#define BSTAGE (DIMV * ASTB)             // 26880

__global__ __launch_bounds__(256, 1)
void moe_mma_kernel(int L) {
    int tileid = blockIdx.x;
    int e = 0, base = 0, cnt = 0, cum = 0;
#pragma unroll
    for (int q = 0; q < NEXP; q++) {
        int cq = g_cnt[L][q];
        int t = (cq + MT - 1) / MT;
        if (tileid >= cum && tileid < cum + t) { e = q; base = (tileid - cum) * MT; cnt = cq; }
        cum += t;
    }
    if (tileid >= cum) return;
    int mr = min(MT, cnt - base);

    extern __shared__ __align__(16) char dsm[];
    __shared__ int   s_tok[MT];
    __shared__ float s_w[MT];
    __shared__ int   s_k[MT];

    int tid = threadIdx.x, wid = tid >> 5, lane = tid & 31;

    if (tid < MT) {
        if (tid < mr) {
            s_tok[tid] = g_list_tok[e][base + tid];
            s_w[tid]   = g_list_w[e][base + tid];
            s_k[tid]   = g_list_k[e][base + tid];
        } else { s_tok[tid] = 0; s_w[tid] = 0.f; s_k[tid] = 0; }
    }
    __syncthreads();

    const __nv_bfloat16* BHsrc = g_Bth + (size_t)(L * NEXP + e) * DIMV * DIMV;
    const __nv_bfloat16* BLsrc = g_Btl + (size_t)(L * NEXP + e) * DIMV * DIMV;

    auto issue = [&](int kc, int buf) {
        int abuf = buf * ASTAGE;
        int bbuf = buf * BSTAGE;
#pragma unroll
        for (int j = 0; j < 3; j++) {                 // A: 128 rows x 6 segs
            int i = tid + j * 256;
            int row = i / 6, seg = i - row * 6;
            size_t src = (size_t)s_tok[row] * DIMV + kc * KC + seg * 8;
            unsigned dst = row * ASTB + seg * 16;
            cp16(smem_u32(dsm + OFF_AH + abuf + dst), g_hh + src);
            cp16(smem_u32(dsm + OFF_AL + abuf + dst), g_hl + src);
        }
        for (int i = tid; i < DIMV * 6; i += 256) {   // B: 240 rows x 6 segs
            int row = i / 6, seg = i - row * 6;
            size_t src = (size_t)row * DIMV + kc * KC + seg * 8;
            unsigned dst = row * ASTB + seg * 16;
            cp16(smem_u32(dsm + OFF_BH + bbuf + dst), BHsrc + src);
            cp16(smem_u32(dsm + OFF_BL + bbuf + dst), BLsrc + src);
        }
        cp_commit();
    };

    int wm = wid & 3;     // 32-row group (two 16-row m-tiles)
    int wn = wid >> 2;    // 120-col n-half

    float acc[2][15][4];
#pragma unroll
    for (int t = 0; t < 2; t++)
#pragma unroll
        for (int nt = 0; nt < 15; nt++)
#pragma unroll
            for (int j = 0; j < 4; j++) acc[t][nt][j] = 0.f;

    issue(0, 0);

    uint32_t sbase = smem_u32(dsm);
    // ldmatrix per-lane offsets:
    // A x4: row = wm*32 + t*16 + (lane&15); k-extra 16B for lanes>=16
    uint32_t a_off = (uint32_t)(wm * 32 + (lane & 15)) * ASTB + ((lane >> 4) << 4);
    // B x4 (2 n-tiles): n = wn*120 + nt2*16 + ((lane>>4)<<3) + (lane&7);
    //   k-extra 16B when bit3 of lane set
    uint32_t b_off = (uint32_t)(wn * 120 + ((lane >> 4) << 3) + (lane & 7)) * ASTB
                   + (((lane >> 3) & 1) << 4);
    // B x2 (last n-tile, lanes 0-15 pattern repeated): n = wn*120+112+(lane&7)
    uint32_t b2_off = (uint32_t)(wn * 120 + 112 + (lane & 7)) * ASTB
                    + (((lane >> 3) & 1) << 4);

    for (int kc = 0; kc < 5; kc++) {
        int buf = kc & 1;
        if (kc + 1 < 5) { issue(kc + 1, buf ^ 1); cp_wait<1>(); }
        else            { cp_wait<0>(); }
        __syncthreads();

        uint32_t AhB = sbase + OFF_AH + buf * ASTAGE;
        uint32_t AlB = sbase + OFF_AL + buf * ASTAGE;
        uint32_t BhB = sbase + OFF_BH + buf * BSTAGE;
        uint32_t BlB = sbase + OFF_BL + buf * BSTAGE;

#pragma unroll
        for (int ks = 0; ks < 3; ks++) {
            uint32_t ah[2][4], al[2][4];
#pragma unroll
            for (int t = 0; t < 2; t++) {
                uint32_t ao = a_off + t * (16 * ASTB) + ks * 32;
                ldsm4(ah[t], AhB + ao);
                ldsm4(al[t], AlB + ao);
            }
#pragma unroll
            for (int nt2 = 0; nt2 < 7; nt2++) {
                uint32_t bo = b_off + nt2 * (16 * ASTB) + ks * 32;
                uint32_t bh[4], bl[4];
                ldsm4(bh, BhB + bo);
                ldsm4(bl, BlB + bo);
#pragma unroll
                for (int t = 0; t < 2; t++) {
                    MMA_BF16(acc[t][2*nt2],   ah[t][0], ah[t][1], ah[t][2], ah[t][3], bh[0], bh[1]);
                    MMA_BF16(acc[t][2*nt2],   ah[t][0], ah[t][1], ah[t][2], ah[t][3], bl[0], bl[1]);
                    MMA_BF16(acc[t][2*nt2],   al[t][0], al[t][1], al[t][2], al[t][3], bh[0], bh[1]);
                    MMA_BF16(acc[t][2*nt2+1], ah[t][0], ah[t][1], ah[t][2], ah[t][3], bh[2], bh[3]);
                    MMA_BF16(acc[t][2*nt2+1], ah[t][0], ah[t][1], ah[t][2], ah[t][3], bl[2], bl[3]);
                    MMA_BF16(acc[t][2*nt2+1], al[t][0], al[t][1], al[t][2], al[t][3], bh[2], bh[3]);
                }
            }
            {   // last n-tile (nt = 14)
                uint32_t bo = b2_off + ks * 32;
                uint32_t bh[2], bl[2];
                ldsm2(bh, BhB + bo);
                ldsm2(bl, BlB + bo);
#pragma unroll
                for (int t = 0; t < 2; t++) {
                    MMA_BF16(acc[t][14], ah[t][0], ah[t][1], ah[t][2], ah[t][3], bh[0], bh[1]);
                    MMA_BF16(acc[t][14], ah[t][0], ah[t][1], ah[t][2], ah[t][3], bl[0], bl[1]);
                    MMA_BF16(acc[t][14], al[t][0], al[t][1], al[t][2], al[t][3], bh[0], bh[1]);
                }
            }
        }
        __syncthreads();
    }

    // ---- scaled stores straight from fragments ----
#pragma unroll
    for (int t = 0; t < 2; t++) {
        int r0 = wm * 32 + t * 16 + (lane >> 2);
        int r1 = r0 + 8;
        int colb = wn * 120 + (lane & 3) * 2;
        bool ok0 = r0 < mr, ok1 = r1 < mr;
        float w0v = s_w[r0], w1v = s_w[r1];
        float* d0 = ok0 ? &g_part[s_k[r0]][(size_t)s_tok[r0] * DIMV] : 0;
        float* d1 = ok1 ? &g_part[s_k[r1]][(size_t)s_tok[r1] * DIMV] : 0;
#pragma unroll
        for (int nt = 0; nt < 15; nt++) {
            int col = colb + nt * 8;
            if (ok0) {
                float2 o; o.x = w0v * acc[t][nt][0]; o.y = w0v * acc[t][nt][1];
                *(float2*)&d0[col] = o;
            }
            if (ok1) {
                float2 o; o.x = w1v * acc[t][nt][2]; o.y = w1v * acc[t][nt][3];
                *(float2*)&d1[col] = o;
            }
        }
    }
}

// ------------- fused: epilogue(L) [+ gate(L+1) if DO_GATE] -------------------
template<int DO_GATE>
__global__ void epi_gate_kernel(const float* __restrict__ eb,
                                const float* __restrict__ gamma,
                                const float* __restrict__ beta,
                                const float* __restrict__ gW,
                                const float* __restrict__ gb,
                                int Lnext) {
    int warp = threadIdx.x >> 5;
    int lane = threadIdx.x & 31;
    int tok  = blockIdx.x * 8 + warp;

    int   e0 = g_route_e[tok * 2 + 0], e1 = g_route_e[tok * 2 + 1];
    float w0 = g_route_w[tok * 2 + 0], w1 = g_route_w[tok * 2 + 1];

    const float* p0 = &g_part[0][(size_t)tok * DIMV];
    const float* p1 = &g_part[1][(size_t)tok * DIMV];

    float v[8];
    float sum = 0.f;
#pragma unroll
    for (int jq = 0; jq < 8; jq++) {
        int d = lane + 32 * jq;
        if (d < DIMV) {
            v[jq] = p0[d] + p1[d] + w0 * eb[e0 * DIMV + d] + w1 * eb[e1 * DIMV + d];
            sum += v[jq];
        } else v[jq] = 0.f;
    }
#pragma unroll
    for (int o = 16; o > 0; o >>= 1) sum += __shfl_xor_sync(0xffffffffu, sum, o);
    float mean = sum * (1.0f / DIMV);

    float vs = 0.f;
#pragma unroll
    for (int jq = 0; jq < 8; jq++) {
        int d = lane + 32 * jq;
        if (d < DIMV) { float c = v[jq] - mean; vs += c * c; }
    }
#pragma unroll
    for (int o = 16; o > 0; o >>= 1) vs += __shfl_xor_sync(0xffffffffu, vs, o);
    float inv = 1.0f / sqrtf(vs * (1.0f / DIMV) + LNEPS);

    float hh[8];
    __nv_bfloat16* hph = &g_hh[(size_t)tok * DIMV];
    __nv_bfloat16* hpl = &g_hl[(size_t)tok * DIMV];
#pragma unroll
    for (int jq = 0; jq < 8; jq++) {
        int d = lane + 32 * jq;
        if (d < DIMV) {
            float ln = (v[jq] - mean) * inv * gamma[d] + beta[d];
            float hv = v[jq] + ln;
            hh[jq] = hv;
            __nv_bfloat16 hi = __float2bfloat16(hv);
            hph[d] = hi;
            hpl[d] = __float2bfloat16(hv - __bfloat162float(hi));
        } else hh[jq] = 0.f;
    }

    if (DO_GATE)
        gate_from_regs(hh, gW, gb, Lnext, lane ? tok : tok, lane);
}

// ------------------------- head (h = hi + lo) --------------------------------
__global__ void head_kernel(const float* __restrict__ hW,
                            const float* __restrict__ hb,
                            float* __restrict__ out) {
    int b = blockIdx.x;
    int tid = threadIdx.x;
    const __nv_bfloat16* hh = g_hh + (size_t)b * SS * DIMV;
    const __nv_bfloat16* hl = g_hl + (size_t)b * SS * DIMV;
    float acc = 0.f;
    for (int i = tid; i < SS * DIMV; i += 256) {
        float h = __bfloat162float(hh[i]) + __bfloat162float(hl[i]);
        acc += h * hW[i % DIMV];
    }
    __shared__ float red[256];
    red[tid] = acc;
    __syncthreads();
    for (int s2 = 128; s2 > 0; s2 >>= 1) {
        if (tid < s2) red[tid] += red[tid + s2];
        __syncthreads();
    }
    if (tid == 0) {
        float z = red[0] * (1.0f / SS) + hb[0];
        out[b] = 1.0f / (1.0f + expf(-z));
    }
}

// ------------------------- launch -------------------------------------------
extern "C" void kernel_launch(void* const* d_in, const int* in_sizes, int n_in,
                              void* d_out, int out_size) {
    const float* x     = (const float*)d_in[0];
    const int*   step  = (const int*)  d_in[1];
    const float* roots = (const float*)d_in[2];
    const float* projW = (const float*)d_in[3];
    const float* gW    = (const float*)d_in[4];
    const float* gb    = (const float*)d_in[5];
    const float* eW    = (const float*)d_in[6];
    const float* ebias = (const float*)d_in[7];
    const float* gamma = (const float*)d_in[8];
    const float* beta  = (const float*)d_in[9];
    const float* hW    = (const float*)d_in[10];
    const float* hb    = (const float*)d_in[11];
    float* out = (float*)d_out;

    cudaFuncSetAttribute(moe_mma_kernel,
                         cudaFuncAttributeMaxDynamicSharedMemorySize, SMEM_DYN);

    setup_kernel<<<240, DIMV>>>(roots, projW);
    {
        dim3 bg(15, NDEPTH * NEXP);
        bconv_kernel<<<bg, 256>>>(eW);
    }
    cycle_kernel<<<NTOK, 256>>>(x, step, gW, gb);

    for (int L = 0; L < NDEPTH; L++) {
        moe_mma_kernel<<<NTILES, 256, SMEM_DYN>>>(L);
        if (L + 1 < NDEPTH) {
            epi_gate_kernel<1><<<NTOK / 8, 256>>>(
                ebias + (size_t)L * NEXP * DIMV, gamma, beta,
                gW + (size_t)(L + 1) * DIMV * NEXP, gb + (size_t)(L + 1) * NEXP,
                L + 1);
        } else {
            epi_gate_kernel<0><<<NTOK / 8, 256>>>(
                ebias + (size_t)L * NEXP * DIMV, gamma, beta,
                gW, gb, 0);
        }
    }

    head_kernel<<<BB, 256>>>(hW, hb, out);
}